// round 7
// baseline (speedup 1.0000x reference)
#include <cuda_runtime.h>
#include <cstdint>

#define BB   256
#define LL   512
#define FF   64
#define LF   32768        // L*F
#define NTOT 8388608      // B*L*F
#define HH   128
#define H2   256
#define ND   64

// ---------------- device globals (scratch; no allocations allowed) ----------
__device__ float  g_sc[8];        // 0:maskmul 1:noisemul 2:s_scale 3:ratio 4:wa 5:wb 6:wc 7:s_mix
__device__ uint2  g_keys[3];      // kz, kn, kf
__device__ int    g_wp[BB], g_sh[BB];
__device__ float  g_z [BB * ND];
__device__ float  g_h1[BB * HH];
__device__ float  g_h2[BB * H2];
__device__ float  g_h3[BB * H2];
__device__ float  g_scale[BB * FF];
__device__ float  g_freq[NTOT];

// ---------------- threefry2x32 (JAX rotation schedule) ----------------------
__device__ __forceinline__ uint2 tf2x32(uint32_t k0, uint32_t k1, uint32_t x0, uint32_t x1) {
    uint32_t k2 = k0 ^ k1 ^ 0x1BD11BDAu;
    x0 += k0; x1 += k1;
#define TFR(r) { x0 += x1; x1 = (x1 << (r)) | (x1 >> (32 - (r))); x1 ^= x0; }
    TFR(13) TFR(15) TFR(26) TFR(6)
    x0 += k1; x1 += k2 + 1u;
    TFR(17) TFR(29) TFR(16) TFR(24)
    x0 += k2; x1 += k0 + 2u;
    TFR(13) TFR(15) TFR(26) TFR(6)
    x0 += k0; x1 += k1 + 3u;
    TFR(17) TFR(29) TFR(16) TFR(24)
    x0 += k1; x1 += k2 + 4u;
    TFR(13) TFR(15) TFR(26) TFR(6)
    x0 += k2; x1 += k0 + 5u;
#undef TFR
    return make_uint2(x0, x1);
}

// partitionable random_bits for 32-bit dtypes (jax/_src/prng.py):
// counts = 64-bit iota split (hi,lo); bits = bits1 ^ bits2 (XOR of both lanes)
__device__ __forceinline__ uint32_t tf_bits(uint2 key, uint32_t e) {
    uint2 r = tf2x32(key.x, key.y, 0u, e);
    return r.x ^ r.y;
}
__device__ __forceinline__ float u01_from_bits(uint32_t bits) {
    return __uint_as_float((bits >> 9) | 0x3f800000u) - 1.0f;
}
// jax.random.normal: sqrt(2)*erfinv(uniform(lo=nextafter(-1,0), hi=1))
__device__ __forceinline__ float tf_normal(uint2 key, uint32_t e) {
    float u = u01_from_bits(tf_bits(key, e));
    const float lo = -0.99999994f;       // nextafter(-1,0) in f32
    float v = u * 2.0f + lo;             // (hi-lo) rounds to exactly 2.0f in f32
    v = fmaxf(lo, v);
    return 1.4142135623730951f * erfinvf(v);
}

__device__ __forceinline__ float sigmf(float x)  { return 1.0f / (1.0f + expf(-x)); }
__device__ __forceinline__ float softplusf(float x) { return fmaxf(x, 0.0f) + log1pf(expf(-fabsf(x))); }

// ---------------- kernel 1: scalars, derived keys, wp/sh randint ------------
__global__ void setup_kernel(const float* __restrict__ p_mask, const float* __restrict__ p_noise,
                             const float* __restrict__ p_shift, const float* __restrict__ p_scale) {
    __shared__ uint2 skwp1, skwp2, sksh1, sksh2;
    __shared__ int   s_ws;
    int tid = threadIdx.x;
    if (tid == 0) {
        // root key = (0, 42); partitionable (foldlike) split: key_i = TF(key, (0, i)), both words
        uint2 kz  = tf2x32(0u, 42u, 0u, 0u);
        uint2 kn  = tf2x32(0u, 42u, 0u, 1u);
        uint2 kwp = tf2x32(0u, 42u, 0u, 2u);
        uint2 ksh = tf2x32(0u, 42u, 0u, 3u);
        uint2 kf  = tf2x32(0u, 42u, 0u, 4u);
        g_keys[0] = kz; g_keys[1] = kn; g_keys[2] = kf;
        // randint internally splits its key again (foldlike)
        skwp1 = tf2x32(kwp.x, kwp.y, 0u, 0u);
        skwp2 = tf2x32(kwp.x, kwp.y, 0u, 1u);
        sksh1 = tf2x32(ksh.x, ksh.y, 0u, 0u);
        sksh2 = tf2x32(ksh.x, ksh.y, 0u, 1u);

        float sm = sigmf(*p_mask), sn = sigmf(*p_noise);
        float ss = sigmf(*p_shift), sc = sigmf(*p_scale);
        float smix = 1.0f - ss;
        float wa = fminf(fmaxf(1.0f - smix - ss, 0.1f), 0.8f);
        float wb = smix * 0.5f, wc = ss * 0.5f;
        float tot = wa + wb + wc;
        g_sc[0] = sm * 0.3f;
        g_sc[1] = sn * 0.05f;
        g_sc[2] = sc;
        g_sc[3] = fminf(smix * 0.1f, 0.5f);
        g_sc[4] = wa / tot; g_sc[5] = wb / tot; g_sc[6] = wc / tot;
        g_sc[7] = smix;
        s_ws = (int)(51.2f * ss);   // (L*0.1*strength).astype(int32), trunc
    }
    __syncthreads();
    int ws = s_ws;
    int b = tid;   // 256 threads = 256 batches
    {   // wp = randint(kwp, (B,1), ws, 512-ws)
        uint32_t span = (uint32_t)max(1, (512 - ws) - ws);
        uint32_t mult = 65536u % span; mult = (mult * mult) % span;
        uint32_t hi = tf_bits(skwp1, (uint32_t)b);
        uint32_t lo = tf_bits(skwp2, (uint32_t)b);
        // JAX _randint: rem(hi,span)*mult + rem(lo,span), then rem(.,span)
        uint32_t off = ((hi % span) * mult + (lo % span)) % span;
        g_wp[b] = ws + (int)off;
    }
    {   // sh = randint(ksh, (B,1), -ws, ws+1)
        uint32_t span = (uint32_t)(2 * ws + 1); if (span == 0u) span = 1u;
        uint32_t mult = 65536u % span; mult = (mult * mult) % span;
        uint32_t hi = tf_bits(sksh1, (uint32_t)b);
        uint32_t lo = tf_bits(sksh2, (uint32_t)b);
        uint32_t off = ((hi % span) * mult + (lo % span)) % span;
        g_sh[b] = -ws + (int)off;
    }
}

// ---------------- kernel 2: z ~ normal(kz, (B,64)) --------------------------
__global__ void z_kernel() {
    uint32_t i = blockIdx.x * blockDim.x + threadIdx.x;  // 16384
    g_z[i] = tf_normal(g_keys[0], i);
}

// ---------------- small MLP GEMMs with leaky relu ----------------------------
__device__ __forceinline__ void mlp_body(const float* __restrict__ A, const float* __restrict__ W,
                                         const float* __restrict__ bias, float* __restrict__ C,
                                         int K, int N) {
    int i = blockIdx.x * blockDim.x + threadIdx.x;
    int m = i / N, n = i % N;
    float acc = bias[n];
    const float* a = A + (size_t)m * K;
#pragma unroll 8
    for (int k = 0; k < K; k++) acc = fmaf(a[k], W[(size_t)k * N + n], acc);
    C[i] = acc > 0.0f ? acc : 0.2f * acc;
}
__global__ void h1_kernel(const float* __restrict__ w, const float* __restrict__ b) { mlp_body(g_z,  w, b, g_h1, ND,  HH); }
__global__ void h2_kernel(const float* __restrict__ w, const float* __restrict__ b) { mlp_body(g_h1, w, b, g_h2, HH,  H2); }
__global__ void h3_kernel(const float* __restrict__ w, const float* __restrict__ b) { mlp_body(g_h2, w, b, g_h3, H2,  H2); }

// ---------------- scale = 1 + (softplus(h3@ws+bs)-0.5)*0.2*s_scale ----------
__global__ void scale_kernel(const float* __restrict__ ws, const float* __restrict__ bs) {
    int i = blockIdx.x * blockDim.x + threadIdx.x;     // 16384 = 256*64
    int m = i >> 6, n = i & 63;
    float acc = bs[n];
    const float* a = g_h3 + (size_t)m * H2;
#pragma unroll 8
    for (int k = 0; k < H2; k++) acc = fmaf(a[k], ws[(size_t)k * FF + n], acc);
    g_scale[i] = 1.0f + (softplusf(acc) - 0.5f) * 0.2f * g_sc[2];
}

// ---------------- FFT aug: per (b,f) column, 512-pt fwd/mask/inv ------------
__global__ __launch_bounds__(256) void fft_kernel(const float* __restrict__ x) {
    __shared__ float2 s[512];
    __shared__ float2 tw[256];
    int tid = threadIdx.x;
    int col = blockIdx.x;               // 0..16383
    int b = col >> 6, f = col & 63;
    const float* xp = x + (size_t)b * LF + f;

    {   // twiddle table: tw[m] = e^{-2*pi*i*m/512}
        float sv, cv;
        sincosf(-6.283185307179586f * (float)tid / 512.0f, &sv, &cv);
        tw[tid] = make_float2(cv, sv);
    }
    // load in bit-reversed order (9-bit reverse)
    for (int j = tid; j < 512; j += 256) {
        int rev = __brev((unsigned)j) >> 23;
        s[rev] = make_float2(xp[(size_t)j * FF], 0.0f);
    }
    __syncthreads();
    // forward FFT
    for (int len = 2; len <= 512; len <<= 1) {
        int half = len >> 1;
        int g = tid / half, k = tid - g * half;
        int pos = g * len + k;
        float2 w = tw[k * (512 / len)];
        float2 a = s[pos], bv = s[pos + half];
        float2 t = make_float2(bv.x * w.x - bv.y * w.y, bv.x * w.y + bv.y * w.x);
        s[pos]        = make_float2(a.x + t.x, a.y + t.y);
        s[pos + half] = make_float2(a.x - t.x, a.y - t.y);
        __syncthreads();
    }
    // keep mask (natural order)
    {
        float ratio = g_sc[3];
        uint2 kf = g_keys[2];
        for (int j = tid; j < 512; j += 256) {
            uint32_t e = (uint32_t)b * (uint32_t)LF + (uint32_t)j * (uint32_t)FF + (uint32_t)f;
            float u = u01_from_bits(tf_bits(kf, e));
            if (!(u > ratio)) s[j] = make_float2(0.0f, 0.0f);
        }
    }
    __syncthreads();
    // bit-reverse permute for inverse pass
    {
        float2 v0 = s[tid], v1 = s[tid + 256];
        __syncthreads();
        s[__brev((unsigned)tid) >> 23]         = v0;
        s[__brev((unsigned)(tid + 256)) >> 23] = v1;
        __syncthreads();
    }
    // inverse FFT (conjugate twiddles), scale 1/512 at the end
    for (int len = 2; len <= 512; len <<= 1) {
        int half = len >> 1;
        int g = tid / half, k = tid - g * half;
        int pos = g * len + k;
        float2 w = tw[k * (512 / len)];
        float2 a = s[pos], bv = s[pos + half];
        float2 t = make_float2(bv.x * w.x + bv.y * w.y, bv.y * w.x - bv.x * w.y);
        s[pos]        = make_float2(a.x + t.x, a.y + t.y);
        s[pos + half] = make_float2(a.x - t.x, a.y - t.y);
        __syncthreads();
    }
    float smix = g_sc[7];
    for (int j = tid; j < 512; j += 256) {
        float val = s[j].x * (1.0f / 512.0f);
        if (smix < 0.01f) val = xp[(size_t)j * FF];
        g_freq[(size_t)b * LF + (size_t)j * FF + f] = val;
    }
}

// ---------------- final: dual GEMM (mask & noise logits) + fused epilogue ---
#define FBM 64
#define FBN 64
#define FBK 32
__global__ __launch_bounds__(256) void final_kernel(const float* __restrict__ x,
                                                    const float* __restrict__ wm, const float* __restrict__ bmv,
                                                    const float* __restrict__ wn, const float* __restrict__ bnv,
                                                    float* __restrict__ out) {
    __shared__ float As[FBK][FBM + 4];   // transposed h3 tile
    __shared__ float Bm[FBK][FBN + 4];
    __shared__ float Bn[FBK][FBN + 4];
    int tid = threadIdx.x;
    int n0 = blockIdx.x * FBN;
    int m0 = blockIdx.y * FBM;
    int tx = tid & 15, ty = tid >> 4;
    float am[4][4] = {}, an[4][4] = {};

    for (int k0 = 0; k0 < H2; k0 += FBK) {
#pragma unroll
        for (int i = tid; i < 512; i += 256) {       // 64 rows x 8 float4
            int m = i >> 3, kq = i & 7;
            float4 v = *(const float4*)&g_h3[(size_t)(m0 + m) * H2 + k0 + kq * 4];
            As[kq * 4 + 0][m] = v.x; As[kq * 4 + 1][m] = v.y;
            As[kq * 4 + 2][m] = v.z; As[kq * 4 + 3][m] = v.w;
        }
#pragma unroll
        for (int i = tid; i < 512; i += 256) {       // 32 rows x 16 float4
            int k = i >> 4, nq = i & 15;
            size_t off = (size_t)(k0 + k) * LF + n0 + nq * 4;
            *(float4*)&Bm[k][nq * 4] = *(const float4*)&wm[off];
            *(float4*)&Bn[k][nq * 4] = *(const float4*)&wn[off];
        }
        __syncthreads();
#pragma unroll
        for (int k = 0; k < FBK; k++) {
            float a4[4], bm4[4], bn4[4];
#pragma unroll
            for (int i = 0; i < 4; i++) a4[i] = As[k][ty * 4 + i];
#pragma unroll
            for (int j = 0; j < 4; j++) { bm4[j] = Bm[k][tx * 4 + j]; bn4[j] = Bn[k][tx * 4 + j]; }
#pragma unroll
            for (int i = 0; i < 4; i++)
#pragma unroll
                for (int j = 0; j < 4; j++) {
                    am[i][j] = fmaf(a4[i], bm4[j], am[i][j]);
                    an[i][j] = fmaf(a4[i], bn4[j], an[i][j]);
                }
        }
        __syncthreads();
    }

    // fused epilogue
    float maskmul = g_sc[0], noisemul = g_sc[1];
    float wa = g_sc[4], wb = g_sc[5], wc = g_sc[6];
    uint2 kn = g_keys[1];
#pragma unroll
    for (int i = 0; i < 4; i++) {
        int b = m0 + ty * 4 + i;
        int wpb = g_wp[b], shb = g_sh[b];
#pragma unroll
        for (int j = 0; j < 4; j++) {
            int col = n0 + tx * 4 + j;
            int l = col >> 6, f = col & 63;
            int idx;
            if (shb > 0)      idx = (l >= wpb) ? min(l + shb, LL - 1) : l;
            else if (shb < 0) idx = (l >= wpb + shb && l < LL + shb) ? (l - shb) : l;
            else              idx = l;
            uint32_t e = (uint32_t)b * (uint32_t)LF + (uint32_t)col;
            float gm = am[i][j] + bmv[col];
            float mask = 1.0f - (1.0f - sigmf(gm)) * maskmul;
            float gn = an[i][j] + bnv[col];
            float nm = softplusf(gn);
            float nv = tf_normal(kn, e);
            float xv = x[(size_t)e];
            float wv = x[(size_t)b * LF + (size_t)idx * FF + f];
            float fv = g_freq[(size_t)e];
            float sc = g_scale[b * FF + f];
            out[(size_t)e] = (xv * mask * sc + nv * nm * noisemul) * wa + fv * wb + wv * wc;
        }
    }
}

// ---------------- launch ------------------------------------------------------
extern "C" void kernel_launch(void* const* d_in, const int* in_sizes, int n_in,
                              void* d_out, int out_size) {
    const float* x   = (const float*)d_in[0];
    // d_in[1] = batch_size (unused; shapes are static)
    const float* w1  = (const float*)d_in[2];
    const float* b1  = (const float*)d_in[3];
    const float* w2  = (const float*)d_in[4];
    const float* b2  = (const float*)d_in[5];
    const float* w3  = (const float*)d_in[6];
    const float* b3  = (const float*)d_in[7];
    const float* wm  = (const float*)d_in[8];
    const float* bm  = (const float*)d_in[9];
    const float* wn  = (const float*)d_in[10];
    const float* bn  = (const float*)d_in[11];
    const float* ws  = (const float*)d_in[12];
    const float* bs  = (const float*)d_in[13];
    const float* pm  = (const float*)d_in[14];
    const float* pn  = (const float*)d_in[15];
    const float* psh = (const float*)d_in[16];
    const float* psc = (const float*)d_in[17];
    float* out = (float*)d_out;

    setup_kernel<<<1, 256>>>(pm, pn, psh, psc);
    z_kernel<<<64, 256>>>();
    h1_kernel<<<BB * HH / 256, 256>>>(w1, b1);
    h2_kernel<<<BB * H2 / 256, 256>>>(w2, b2);
    h3_kernel<<<BB * H2 / 256, 256>>>(w3, b3);
    scale_kernel<<<BB * FF / 256, 256>>>(ws, bs);
    fft_kernel<<<BB * FF, 256>>>(x);
    final_kernel<<<dim3(LF / FBN, BB / FBM), 256>>>(x, wm, bm, wn, bn, out);
}

// round 9
// speedup vs baseline: 1.1590x; 1.1590x over previous
#include <cuda_runtime.h>
#include <cuda_bf16.h>
#include <mma.h>
#include <cstdint>

using namespace nvcuda;

#define BB   256
#define LL   512
#define FF   64
#define LF   32768
#define NTOT 8388608
#define HH   128
#define H2   256
#define ND   64

// ---------------- device globals ----------------
__device__ float  g_sc[8];        // 0:maskmul 1:noisemul 2:s_scale 3:ratio 4:wa 5:wb 6:wc 7:s_mix
__device__ uint2  g_keys[3];      // kz, kn, kf
__device__ int    g_wp[BB], g_sh[BB];
__device__ __align__(16) uint32_t g_h3b[BB * (H2 / 2)];   // h3 as bf16x2: [256 rows][256 bf16]
__device__ float  g_scale[BB * FF];
__device__ float  g_freq[NTOT];

// ---------------- threefry2x32 (JAX) ----------------
__device__ __forceinline__ uint2 tf2x32(uint32_t k0, uint32_t k1, uint32_t x0, uint32_t x1) {
    uint32_t k2 = k0 ^ k1 ^ 0x1BD11BDAu;
    x0 += k0; x1 += k1;
#define TFR(r) { x0 += x1; x1 = (x1 << (r)) | (x1 >> (32 - (r))); x1 ^= x0; }
    TFR(13) TFR(15) TFR(26) TFR(6)
    x0 += k1; x1 += k2 + 1u;
    TFR(17) TFR(29) TFR(16) TFR(24)
    x0 += k2; x1 += k0 + 2u;
    TFR(13) TFR(15) TFR(26) TFR(6)
    x0 += k0; x1 += k1 + 3u;
    TFR(17) TFR(29) TFR(16) TFR(24)
    x0 += k1; x1 += k2 + 4u;
    TFR(13) TFR(15) TFR(26) TFR(6)
    x0 += k2; x1 += k0 + 5u;
#undef TFR
    return make_uint2(x0, x1);
}
__device__ __forceinline__ uint32_t tf_bits(uint2 key, uint32_t e) {
    uint2 r = tf2x32(key.x, key.y, 0u, e);
    return r.x ^ r.y;
}
__device__ __forceinline__ float u01_from_bits(uint32_t bits) {
    return __uint_as_float((bits >> 9) | 0x3f800000u) - 1.0f;
}
__device__ __forceinline__ float tf_normal(uint2 key, uint32_t e) {
    float u = u01_from_bits(tf_bits(key, e));
    const float lo = -0.99999994f;
    float v = u * 2.0f + lo;
    v = fmaxf(lo, v);
    return 1.4142135623730951f * erfinvf(v);
}
__device__ __forceinline__ float sigmf(float x)  { return 1.0f / (1.0f + expf(-x)); }
__device__ __forceinline__ float softplusf(float x) { return fmaxf(x, 0.0f) + log1pf(expf(-fabsf(x))); }

// ---------------- kernel 1: setup (identical to passing R7 version) ----------
__global__ void setup_kernel(const float* __restrict__ p_mask, const float* __restrict__ p_noise,
                             const float* __restrict__ p_shift, const float* __restrict__ p_scale) {
    __shared__ uint2 skwp1, skwp2, sksh1, sksh2;
    __shared__ int   s_ws;
    int tid = threadIdx.x;
    if (tid == 0) {
        uint2 kz  = tf2x32(0u, 42u, 0u, 0u);
        uint2 kn  = tf2x32(0u, 42u, 0u, 1u);
        uint2 kwp = tf2x32(0u, 42u, 0u, 2u);
        uint2 ksh = tf2x32(0u, 42u, 0u, 3u);
        uint2 kf  = tf2x32(0u, 42u, 0u, 4u);
        g_keys[0] = kz; g_keys[1] = kn; g_keys[2] = kf;
        skwp1 = tf2x32(kwp.x, kwp.y, 0u, 0u);
        skwp2 = tf2x32(kwp.x, kwp.y, 0u, 1u);
        sksh1 = tf2x32(ksh.x, ksh.y, 0u, 0u);
        sksh2 = tf2x32(ksh.x, ksh.y, 0u, 1u);
        float sm = sigmf(*p_mask), sn = sigmf(*p_noise);
        float ss = sigmf(*p_shift), sc = sigmf(*p_scale);
        float smix = 1.0f - ss;
        float wa = fminf(fmaxf(1.0f - smix - ss, 0.1f), 0.8f);
        float wb = smix * 0.5f, wc = ss * 0.5f;
        float tot = wa + wb + wc;
        g_sc[0] = sm * 0.3f; g_sc[1] = sn * 0.05f; g_sc[2] = sc;
        g_sc[3] = fminf(smix * 0.1f, 0.5f);
        g_sc[4] = wa / tot; g_sc[5] = wb / tot; g_sc[6] = wc / tot;
        g_sc[7] = smix;
        s_ws = (int)(51.2f * ss);
    }
    __syncthreads();
    int ws = s_ws;
    int b = tid;
    {
        uint32_t span = (uint32_t)max(1, (512 - ws) - ws);
        uint32_t mult = 65536u % span; mult = (mult * mult) % span;
        uint32_t hi = tf_bits(skwp1, (uint32_t)b);
        uint32_t lo = tf_bits(skwp2, (uint32_t)b);
        uint32_t off = ((hi % span) * mult + (lo % span)) % span;
        g_wp[b] = ws + (int)off;
    }
    {
        uint32_t span = (uint32_t)(2 * ws + 1); if (span == 0u) span = 1u;
        uint32_t mult = 65536u % span; mult = (mult * mult) % span;
        uint32_t hi = tf_bits(sksh1, (uint32_t)b);
        uint32_t lo = tf_bits(sksh2, (uint32_t)b);
        uint32_t off = ((hi % span) * mult + (lo % span)) % span;
        g_sh[b] = -ws + (int)off;
    }
}

// ---------------- kernel 2: fused z -> h1 -> h2 -> h3 -> scale ---------------
__global__ __launch_bounds__(256) void mlp_fused(
    const float* __restrict__ w1, const float* __restrict__ b1,
    const float* __restrict__ w2, const float* __restrict__ b2,
    const float* __restrict__ w3, const float* __restrict__ b3,
    const float* __restrict__ ws, const float* __restrict__ bs)
{
    __shared__ float zb[ND], h1b[HH], h2b[H2], h3b[H2];
    int m = blockIdx.x, t = threadIdx.x;
    if (t < ND) zb[t] = tf_normal(g_keys[0], (uint32_t)(m * ND + t));
    __syncthreads();
    if (t < HH) {
        float acc = b1[t];
#pragma unroll 8
        for (int k = 0; k < ND; k++) acc = fmaf(zb[k], w1[k * HH + t], acc);
        h1b[t] = acc > 0.0f ? acc : 0.2f * acc;
    }
    __syncthreads();
    {
        float acc = b2[t];
#pragma unroll 8
        for (int k = 0; k < HH; k++) acc = fmaf(h1b[k], w2[k * H2 + t], acc);
        h2b[t] = acc > 0.0f ? acc : 0.2f * acc;
    }
    __syncthreads();
    {
        float acc = b3[t];
#pragma unroll 8
        for (int k = 0; k < H2; k++) acc = fmaf(h2b[k], w3[k * H2 + t], acc);
        h3b[t] = acc > 0.0f ? acc : 0.2f * acc;
    }
    __syncthreads();
    if (t < H2 / 2) {
        __nv_bfloat162 p = __floats2bfloat162_rn(h3b[2 * t], h3b[2 * t + 1]);
        g_h3b[m * (H2 / 2) + t] = *reinterpret_cast<uint32_t*>(&p);
    }
    if (t < FF) {
        float acc = bs[t];
#pragma unroll 8
        for (int k = 0; k < H2; k++) acc = fmaf(h3b[k], ws[k * FF + t], acc);
        g_scale[m * FF + t] = 1.0f + (softplusf(acc) - 0.5f) * 0.2f * g_sc[2];
    }
}

// ---------------- kernel 3: FFT aug, 8 columns per block (coalesced) --------
__global__ __launch_bounds__(256) void fft_kernel8(const float* __restrict__ x) {
    __shared__ float2 s[512][9];
    __shared__ float2 tw[256];
    int tid = threadIdx.x;
    int bidx = blockIdx.x;            // 2048 blocks
    int b = bidx >> 3;
    int f0 = (bidx & 7) * 8;
    const float* xp = x + (size_t)b * LF + f0;
    {
        float sv, cv;
        sincosf(-6.283185307179586f * (float)tid / 512.0f, &sv, &cv);
        tw[tid] = make_float2(cv, sv);
    }
#pragma unroll
    for (int it = 0; it < 16; it++) {
        int u = it * 256 + tid;
        int ff = u & 7, l = u >> 3;
        int rev = __brev((unsigned)l) >> 23;
        s[rev][ff] = make_float2(xp[(size_t)l * FF + ff], 0.0f);
    }
    __syncthreads();
    for (int len = 2; len <= 512; len <<= 1) {
        int half = len >> 1;
#pragma unroll
        for (int it = 0; it < 8; it++) {
            int u = it * 256 + tid;
            int ff = u & 7, bi = u >> 3;
            int g = bi / half, k = bi - g * half;
            int pos = g * len + k;
            float2 w = tw[k * (512 / len)];
            float2 a = s[pos][ff], bv = s[pos + half][ff];
            float2 t2 = make_float2(bv.x * w.x - bv.y * w.y, bv.x * w.y + bv.y * w.x);
            s[pos][ff]        = make_float2(a.x + t2.x, a.y + t2.y);
            s[pos + half][ff] = make_float2(a.x - t2.x, a.y - t2.y);
        }
        __syncthreads();
    }
    {
        float ratio = g_sc[3];
        uint2 kf = g_keys[2];
#pragma unroll
        for (int it = 0; it < 16; it++) {
            int u = it * 256 + tid;
            int ff = u & 7, j = u >> 3;
            uint32_t e = (uint32_t)b * LF + (uint32_t)j * FF + (uint32_t)(f0 + ff);
            float uu = u01_from_bits(tf_bits(kf, e));
            if (!(uu > ratio)) s[j][ff] = make_float2(0.0f, 0.0f);
        }
    }
    __syncthreads();
    {
        float2 v[16];
#pragma unroll
        for (int it = 0; it < 16; it++) { int u = it * 256 + tid; v[it] = s[u >> 3][u & 7]; }
        __syncthreads();
#pragma unroll
        for (int it = 0; it < 16; it++) {
            int u = it * 256 + tid; int l = u >> 3, ff = u & 7;
            s[__brev((unsigned)l) >> 23][ff] = v[it];
        }
    }
    __syncthreads();
    for (int len = 2; len <= 512; len <<= 1) {
        int half = len >> 1;
#pragma unroll
        for (int it = 0; it < 8; it++) {
            int u = it * 256 + tid;
            int ff = u & 7, bi = u >> 3;
            int g = bi / half, k = bi - g * half;
            int pos = g * len + k;
            float2 w = tw[k * (512 / len)];
            float2 a = s[pos][ff], bv = s[pos + half][ff];
            float2 t2 = make_float2(bv.x * w.x + bv.y * w.y, bv.y * w.x - bv.x * w.y);
            s[pos][ff]        = make_float2(a.x + t2.x, a.y + t2.y);
            s[pos + half][ff] = make_float2(a.x - t2.x, a.y - t2.y);
        }
        __syncthreads();
    }
    float smix = g_sc[7];
#pragma unroll
    for (int it = 0; it < 16; it++) {
        int u = it * 256 + tid;
        int ff = u & 7, l = u >> 3;
        float val = s[l][ff].x * (1.0f / 512.0f);
        if (smix < 0.01f) val = xp[(size_t)l * FF + ff];
        g_freq[(size_t)b * LF + (size_t)l * FF + f0 + ff] = val;
    }
}

// ---------------- kernel 4: wmma bf16 dual GEMM + fused epilogue ------------
// grid (512 n-tiles, 2 m-blocks), 128 threads (4 warps). Per CTA: M=128, N=64, K=256.
#define BLD  72                       // B tile leading dim (bf16 elems)
#define STG  68                       // stage leading dim (floats, mult of 4)
#define SM_B   0                      // bf16 [16][72] = 2304 B
#define SM_ST  2560                   // float [2][128][68]
#define DYN_SMEM (2560 + 2 * 128 * STG * 4)   // 72192 B

__global__ __launch_bounds__(128) void final_mma(
    const float* __restrict__ x,
    const float* __restrict__ wm, const float* __restrict__ bmv,
    const float* __restrict__ wn, const float* __restrict__ bnv,
    float* __restrict__ out)
{
    extern __shared__ char smem[];
    __nv_bfloat16* Bt = reinterpret_cast<__nv_bfloat16*>(smem + SM_B);
    float* stage = reinterpret_cast<float*>(smem + SM_ST);
    int tid = threadIdx.x;
    int wid = tid >> 5;
    int n0 = blockIdx.x * 64;
    int l_idx = blockIdx.x;
    int m0 = blockIdx.y * 128;
    const __nv_bfloat16* Ag = reinterpret_cast<const __nv_bfloat16*>(g_h3b);

#pragma unroll
    for (int g = 0; g < 2; g++) {
        const float* w = g ? wn : wm;
        float* stg = stage + g * 128 * STG;
        wmma::fragment<wmma::accumulator, 16, 16, 16, float> acc[2][4];
#pragma unroll
        for (int mi = 0; mi < 2; mi++)
#pragma unroll
            for (int ni = 0; ni < 4; ni++) wmma::fill_fragment(acc[mi][ni], 0.0f);

        for (int kt = 0; kt < 16; kt++) {
            int k0 = kt * 16;
            // load + convert B tile [16 k][64 n] fp32 -> bf16 smem
            {
                int r = tid >> 3, c = (tid & 7) * 8;
                const float4* src = reinterpret_cast<const float4*>(w + (size_t)(k0 + r) * LF + n0 + c);
                float4 v0 = src[0], v1 = src[1];
                __nv_bfloat162 p0 = __floats2bfloat162_rn(v0.x, v0.y);
                __nv_bfloat162 p1 = __floats2bfloat162_rn(v0.z, v0.w);
                __nv_bfloat162 p2 = __floats2bfloat162_rn(v1.x, v1.y);
                __nv_bfloat162 p3 = __floats2bfloat162_rn(v1.z, v1.w);
                uint4 pk = make_uint4(*reinterpret_cast<uint32_t*>(&p0), *reinterpret_cast<uint32_t*>(&p1),
                                      *reinterpret_cast<uint32_t*>(&p2), *reinterpret_cast<uint32_t*>(&p3));
                *reinterpret_cast<uint4*>(Bt + r * BLD + c) = pk;
            }
            __syncthreads();
            wmma::fragment<wmma::matrix_a, 16, 16, 16, __nv_bfloat16, wmma::row_major> af[2];
#pragma unroll
            for (int mi = 0; mi < 2; mi++)
                wmma::load_matrix_sync(af[mi], Ag + (size_t)(m0 + wid * 32 + mi * 16) * H2 + k0, H2);
#pragma unroll
            for (int ni = 0; ni < 4; ni++) {
                wmma::fragment<wmma::matrix_b, 16, 16, 16, __nv_bfloat16, wmma::row_major> bf;
                wmma::load_matrix_sync(bf, Bt + ni * 16, BLD);
#pragma unroll
                for (int mi = 0; mi < 2; mi++)
                    wmma::mma_sync(acc[mi][ni], af[mi], bf, acc[mi][ni]);
            }
            __syncthreads();
        }
#pragma unroll
        for (int mi = 0; mi < 2; mi++)
#pragma unroll
            for (int ni = 0; ni < 4; ni++)
                wmma::store_matrix_sync(stg + (size_t)(wid * 32 + mi * 16) * STG + ni * 16,
                                        acc[mi][ni], STG, wmma::mem_row_major);
    }
    __syncthreads();

    // ---- fused epilogue (identical semantics to passing R7 version) ----
    float maskmul = g_sc[0], noisemul = g_sc[1];
    float wa = g_sc[4], wb = g_sc[5], wc = g_sc[6];
    uint2 kn = g_keys[1];
    const float* gmSb = stage;
    const float* gnSb = stage + 128 * STG;
    for (int i = tid; i < 8192; i += 128) {
        int r = i >> 6, c = i & 63;
        int b = m0 + r;
        int col = n0 + c;
        int f = c, l = l_idx;
        int wpb = g_wp[b], shb = g_sh[b];
        int idx;
        if (shb > 0)      idx = (l >= wpb) ? min(l + shb, LL - 1) : l;
        else if (shb < 0) idx = (l >= wpb + shb && l < LL + shb) ? (l - shb) : l;
        else              idx = l;
        uint32_t e = (uint32_t)b * LF + (uint32_t)col;
        float gm = gmSb[r * STG + c] + bmv[col];
        float mask = 1.0f - (1.0f - sigmf(gm)) * maskmul;
        float gn = gnSb[r * STG + c] + bnv[col];
        float nm = softplusf(gn);
        float nv = tf_normal(kn, e);
        float xv = x[(size_t)e];
        float wv = x[(size_t)b * LF + (size_t)idx * FF + f];
        float fv = g_freq[(size_t)e];
        float sc = g_scale[b * FF + f];
        out[(size_t)e] = (xv * mask * sc + nv * nm * noisemul) * wa + fv * wb + wv * wc;
    }
}

// ---------------- launch ------------------------------------------------------
extern "C" void kernel_launch(void* const* d_in, const int* in_sizes, int n_in,
                              void* d_out, int out_size) {
    const float* x   = (const float*)d_in[0];
    const float* w1  = (const float*)d_in[2];
    const float* b1  = (const float*)d_in[3];
    const float* w2  = (const float*)d_in[4];
    const float* b2  = (const float*)d_in[5];
    const float* w3  = (const float*)d_in[6];
    const float* b3  = (const float*)d_in[7];
    const float* wm  = (const float*)d_in[8];
    const float* bm  = (const float*)d_in[9];
    const float* wn  = (const float*)d_in[10];
    const float* bn  = (const float*)d_in[11];
    const float* ws  = (const float*)d_in[12];
    const float* bs  = (const float*)d_in[13];
    const float* pm  = (const float*)d_in[14];
    const float* pn  = (const float*)d_in[15];
    const float* psh = (const float*)d_in[16];
    const float* psc = (const float*)d_in[17];
    float* out = (float*)d_out;

    cudaFuncSetAttribute(final_mma, cudaFuncAttributeMaxDynamicSharedMemorySize, DYN_SMEM);

    setup_kernel<<<1, 256>>>(pm, pn, psh, psc);
    mlp_fused<<<256, 256>>>(w1, b1, w2, b2, w3, b3, ws, bs);
    fft_kernel8<<<2048, 256>>>(x);
    final_mma<<<dim3(512, 2), 128, DYN_SMEM>>>(x, wm, bm, wn, bn, out);
}

// round 10
// speedup vs baseline: 1.5741x; 1.3581x over previous
#include <cuda_runtime.h>
#include <cuda_bf16.h>
#include <mma.h>
#include <cstdint>

using namespace nvcuda;

#define BB   256
#define LL   512
#define FF   64
#define LF   32768
#define NTOT 8388608
#define HH   128
#define H2   256
#define ND   64

// ---------------- device globals ----------------
__device__ float  g_sc[8];        // 0:maskmul 1:noisemul 2:s_scale 3:ratio 4:wa 5:wb 6:wc 7:s_mix
__device__ uint2  g_keys[3];      // kz, kn, kf
__device__ int    g_wp[BB], g_sh[BB];
__device__ __align__(16) uint32_t g_h3b[BB * (H2 / 2)];   // h3 bf16: [256 rows][256]
__device__ float  g_scale[BB * FF];
__device__ float  g_freq[NTOT];

// ---------------- threefry2x32 (JAX) ----------------
__device__ __forceinline__ uint2 tf2x32(uint32_t k0, uint32_t k1, uint32_t x0, uint32_t x1) {
    uint32_t k2 = k0 ^ k1 ^ 0x1BD11BDAu;
    x0 += k0; x1 += k1;
#define TFR(r) { x0 += x1; x1 = (x1 << (r)) | (x1 >> (32 - (r))); x1 ^= x0; }
    TFR(13) TFR(15) TFR(26) TFR(6)
    x0 += k1; x1 += k2 + 1u;
    TFR(17) TFR(29) TFR(16) TFR(24)
    x0 += k2; x1 += k0 + 2u;
    TFR(13) TFR(15) TFR(26) TFR(6)
    x0 += k0; x1 += k1 + 3u;
    TFR(17) TFR(29) TFR(16) TFR(24)
    x0 += k1; x1 += k2 + 4u;
    TFR(13) TFR(15) TFR(26) TFR(6)
    x0 += k2; x1 += k0 + 5u;
#undef TFR
    return make_uint2(x0, x1);
}
__device__ __forceinline__ uint32_t tf_bits(uint2 key, uint32_t e) {
    uint2 r = tf2x32(key.x, key.y, 0u, e);
    return r.x ^ r.y;
}
__device__ __forceinline__ float u01_from_bits(uint32_t bits) {
    return __uint_as_float((bits >> 9) | 0x3f800000u) - 1.0f;
}
__device__ __forceinline__ float tf_normal(uint2 key, uint32_t e) {
    float u = u01_from_bits(tf_bits(key, e));
    const float lo = -0.99999994f;
    float v = u * 2.0f + lo;
    v = fmaxf(lo, v);
    return 1.4142135623730951f * erfinvf(v);
}
__device__ __forceinline__ float sigmf(float x)  { return 1.0f / (1.0f + expf(-x)); }
__device__ __forceinline__ float softplusf(float x) { return fmaxf(x, 0.0f) + log1pf(expf(-fabsf(x))); }

// ---------------- kernel 1: setup ----------------
__global__ void setup_kernel(const float* __restrict__ p_mask, const float* __restrict__ p_noise,
                             const float* __restrict__ p_shift, const float* __restrict__ p_scale) {
    __shared__ uint2 skwp1, skwp2, sksh1, sksh2;
    __shared__ int   s_ws;
    int tid = threadIdx.x;
    if (tid == 0) {
        uint2 kz  = tf2x32(0u, 42u, 0u, 0u);
        uint2 kn  = tf2x32(0u, 42u, 0u, 1u);
        uint2 kwp = tf2x32(0u, 42u, 0u, 2u);
        uint2 ksh = tf2x32(0u, 42u, 0u, 3u);
        uint2 kf  = tf2x32(0u, 42u, 0u, 4u);
        g_keys[0] = kz; g_keys[1] = kn; g_keys[2] = kf;
        skwp1 = tf2x32(kwp.x, kwp.y, 0u, 0u);
        skwp2 = tf2x32(kwp.x, kwp.y, 0u, 1u);
        sksh1 = tf2x32(ksh.x, ksh.y, 0u, 0u);
        sksh2 = tf2x32(ksh.x, ksh.y, 0u, 1u);
        float sm = sigmf(*p_mask), sn = sigmf(*p_noise);
        float ss = sigmf(*p_shift), sc = sigmf(*p_scale);
        float smix = 1.0f - ss;
        float wa = fminf(fmaxf(1.0f - smix - ss, 0.1f), 0.8f);
        float wb = smix * 0.5f, wc = ss * 0.5f;
        float tot = wa + wb + wc;
        g_sc[0] = sm * 0.3f; g_sc[1] = sn * 0.05f; g_sc[2] = sc;
        g_sc[3] = fminf(smix * 0.1f, 0.5f);
        g_sc[4] = wa / tot; g_sc[5] = wb / tot; g_sc[6] = wc / tot;
        g_sc[7] = smix;
        s_ws = (int)(51.2f * ss);
    }
    __syncthreads();
    int ws = s_ws;
    int b = tid;
    {
        uint32_t span = (uint32_t)max(1, (512 - ws) - ws);
        uint32_t mult = 65536u % span; mult = (mult * mult) % span;
        uint32_t hi = tf_bits(skwp1, (uint32_t)b);
        uint32_t lo = tf_bits(skwp2, (uint32_t)b);
        uint32_t off = ((hi % span) * mult + (lo % span)) % span;
        g_wp[b] = ws + (int)off;
    }
    {
        uint32_t span = (uint32_t)(2 * ws + 1); if (span == 0u) span = 1u;
        uint32_t mult = 65536u % span; mult = (mult * mult) % span;
        uint32_t hi = tf_bits(sksh1, (uint32_t)b);
        uint32_t lo = tf_bits(sksh2, (uint32_t)b);
        uint32_t off = ((hi % span) * mult + (lo % span)) % span;
        g_sh[b] = -ws + (int)off;
    }
}

// ---------------- kernel 2: combined FFT-aug (blocks 0..2047) + MLP (2048..2303)
__global__ __launch_bounds__(256) void fft_mlp(
    const float* __restrict__ x,
    const float* __restrict__ w1, const float* __restrict__ b1,
    const float* __restrict__ w2, const float* __restrict__ b2,
    const float* __restrict__ w3, const float* __restrict__ b3,
    const float* __restrict__ ws, const float* __restrict__ bs)
{
    __shared__ float2 s[512][9];
    __shared__ float2 tw[256];
    __shared__ float zb[ND], h1b[HH], h2b[H2], h3b[H2];
    int tid = threadIdx.x;

    if (blockIdx.x >= 2048) {
        // ------- MLP path -------
        int m = blockIdx.x - 2048, t = tid;
        if (t < ND) zb[t] = tf_normal(g_keys[0], (uint32_t)(m * ND + t));
        __syncthreads();
        if (t < HH) {
            float acc = b1[t];
#pragma unroll 8
            for (int k = 0; k < ND; k++) acc = fmaf(zb[k], w1[k * HH + t], acc);
            h1b[t] = acc > 0.0f ? acc : 0.2f * acc;
        }
        __syncthreads();
        {
            float acc = b2[t];
#pragma unroll 8
            for (int k = 0; k < HH; k++) acc = fmaf(h1b[k], w2[k * H2 + t], acc);
            h2b[t] = acc > 0.0f ? acc : 0.2f * acc;
        }
        __syncthreads();
        {
            float acc = b3[t];
#pragma unroll 8
            for (int k = 0; k < H2; k++) acc = fmaf(h2b[k], w3[k * H2 + t], acc);
            h3b[t] = acc > 0.0f ? acc : 0.2f * acc;
        }
        __syncthreads();
        if (t < H2 / 2) {
            __nv_bfloat162 p = __floats2bfloat162_rn(h3b[2 * t], h3b[2 * t + 1]);
            g_h3b[m * (H2 / 2) + t] = *reinterpret_cast<uint32_t*>(&p);
        }
        if (t < FF) {
            float acc = bs[t];
#pragma unroll 8
            for (int k = 0; k < H2; k++) acc = fmaf(h3b[k], ws[k * FF + t], acc);
            g_scale[m * FF + t] = 1.0f + (softplusf(acc) - 0.5f) * 0.2f * g_sc[2];
        }
        return;
    }

    // ------- FFT path: 8 f-columns per block, DIF fwd -> mask -> DIT inv -------
    int bidx = blockIdx.x;
    int b = bidx >> 3;
    int f0 = (bidx & 7) * 8;
    const float* xp = x + (size_t)b * LF + f0;
    {
        float sv, cv;
        sincosf(-6.283185307179586f * (float)tid / 512.0f, &sv, &cv);
        tw[tid] = make_float2(cv, sv);
    }
    // natural-order load (coalesced)
#pragma unroll
    for (int it = 0; it < 16; it++) {
        int u = it * 256 + tid;
        int ff = u & 7, l = u >> 3;
        s[l][ff] = make_float2(xp[(size_t)l * FF + ff], 0.0f);
    }
    __syncthreads();
    // forward DIF: len 512 -> 2; output bit-reversed
#pragma unroll
    for (int st = 0; st < 9; st++) {
        const int half = 256 >> st;
        for (int it = 0; it < 8; it++) {
            int u = it * 256 + tid;
            int ff = u & 7, bi = u >> 3;          // bi in [0,256)
            int k = bi & (half - 1);
            int g = bi >> (8 - st);
            int pos = (g << (9 - st)) + k;
            float2 w = tw[k << st];
            float2 a = s[pos][ff], bv = s[pos + half][ff];
            float2 d = make_float2(a.x - bv.x, a.y - bv.y);
            s[pos][ff]        = make_float2(a.x + bv.x, a.y + bv.y);
            s[pos + half][ff] = make_float2(d.x * w.x - d.y * w.y, d.x * w.y + d.y * w.x);
        }
        __syncthreads();
    }
    // keep mask at bit-reversed positions: freq j = brev9(p)
    {
        float ratio = g_sc[3];
        uint2 kf = g_keys[2];
#pragma unroll
        for (int it = 0; it < 16; it++) {
            int u = it * 256 + tid;
            int ff = u & 7, p = u >> 3;
            int j = (int)(__brev((unsigned)p) >> 23);
            uint32_t e = (uint32_t)b * LF + (uint32_t)j * FF + (uint32_t)(f0 + ff);
            float uu = u01_from_bits(tf_bits(kf, e));
            if (!(uu > ratio)) s[p][ff] = make_float2(0.0f, 0.0f);
        }
    }
    __syncthreads();
    // inverse DIT: len 2 -> 512, conj twiddles; bit-rev in, natural out
#pragma unroll
    for (int st = 0; st < 9; st++) {
        const int half = 1 << st;
        for (int it = 0; it < 8; it++) {
            int u = it * 256 + tid;
            int ff = u & 7, bi = u >> 3;
            int k = bi & (half - 1);
            int g = bi >> st;
            int pos = (g << (st + 1)) + k;
            float2 w = tw[k << (8 - st)];
            float2 a = s[pos][ff], bv = s[pos + half][ff];
            // t = conj(w) * bv
            float2 t = make_float2(w.x * bv.x + w.y * bv.y, w.x * bv.y - w.y * bv.x);
            s[pos][ff]        = make_float2(a.x + t.x, a.y + t.y);
            s[pos + half][ff] = make_float2(a.x - t.x, a.y - t.y);
        }
        __syncthreads();
    }
    float smix = g_sc[7];
#pragma unroll
    for (int it = 0; it < 16; it++) {
        int u = it * 256 + tid;
        int ff = u & 7, l = u >> 3;
        float val = s[l][ff].x * (1.0f / 512.0f);
        if (smix < 0.01f) val = xp[(size_t)l * FF + ff];
        g_freq[(size_t)b * LF + (size_t)l * FF + f0 + ff] = val;
    }
}

// ---------------- kernel 3: wmma bf16 dual GEMM + fused epilogue ------------
// grid (512 n-tiles, 2 m-blocks), 256 threads (8 warps). Per CTA: M=128, N=64, K=256.
#define BPLD 72                       // B panel leading dim (bf16 elems)
#define STG  68                       // stage leading dim (floats)
#define SM_ST 36864                   // after bf16 panel [256][72] = 36864 B
#define DYN_SMEM (36864 + 2 * 128 * STG * 4)   // 106496 B

__global__ __launch_bounds__(256) void final_mma(
    const float* __restrict__ x,
    const float* __restrict__ wm, const float* __restrict__ bmv,
    const float* __restrict__ wn, const float* __restrict__ bnv,
    float* __restrict__ out)
{
    extern __shared__ char smem[];
    __nv_bfloat16* Bt = reinterpret_cast<__nv_bfloat16*>(smem);
    float* stage = reinterpret_cast<float*>(smem + SM_ST);
    int tid = threadIdx.x;
    int wid = tid >> 5;
    int n0 = blockIdx.x * 64;
    int l_idx = blockIdx.x;
    int m0 = blockIdx.y * 128;
    const __nv_bfloat16* Ag = reinterpret_cast<const __nv_bfloat16*>(g_h3b);

#pragma unroll
    for (int gsel = 0; gsel < 2; gsel++) {
        const float* w = gsel ? wn : wm;
        // ---- preload full B panel K=256 x N=64, fp32 -> bf16 smem (no per-k syncs after) ----
#pragma unroll
        for (int i = 0; i < 8; i++) {
            int u = i * 256 + tid;               // 2048 chunks of 8 floats
            int r = u >> 3, c = (u & 7) * 8;
            const float4* src = reinterpret_cast<const float4*>(w + (size_t)r * LF + n0 + c);
            float4 v0 = src[0], v1 = src[1];
            __nv_bfloat162 p0 = __floats2bfloat162_rn(v0.x, v0.y);
            __nv_bfloat162 p1 = __floats2bfloat162_rn(v0.z, v0.w);
            __nv_bfloat162 p2 = __floats2bfloat162_rn(v1.x, v1.y);
            __nv_bfloat162 p3 = __floats2bfloat162_rn(v1.z, v1.w);
            uint4 pk = make_uint4(*reinterpret_cast<uint32_t*>(&p0), *reinterpret_cast<uint32_t*>(&p1),
                                  *reinterpret_cast<uint32_t*>(&p2), *reinterpret_cast<uint32_t*>(&p3));
            *reinterpret_cast<uint4*>(Bt + r * BPLD + c) = pk;
        }
        __syncthreads();

        wmma::fragment<wmma::accumulator, 16, 16, 16, float> acc[4];
#pragma unroll
        for (int ni = 0; ni < 4; ni++) wmma::fill_fragment(acc[ni], 0.0f);

#pragma unroll
        for (int kt = 0; kt < 16; kt++) {
            wmma::fragment<wmma::matrix_a, 16, 16, 16, __nv_bfloat16, wmma::row_major> af;
            wmma::load_matrix_sync(af, Ag + (size_t)(m0 + wid * 16) * H2 + kt * 16, H2);
#pragma unroll
            for (int ni = 0; ni < 4; ni++) {
                wmma::fragment<wmma::matrix_b, 16, 16, 16, __nv_bfloat16, wmma::row_major> bf;
                wmma::load_matrix_sync(bf, Bt + (size_t)kt * 16 * BPLD + ni * 16, BPLD);
                wmma::mma_sync(acc[ni], af, bf, acc[ni]);
            }
        }
        float* stg = stage + gsel * 128 * STG;
#pragma unroll
        for (int ni = 0; ni < 4; ni++)
            wmma::store_matrix_sync(stg + (size_t)(wid * 16) * STG + ni * 16, acc[ni], STG, wmma::mem_row_major);
        __syncthreads();
    }

    // ---- fused epilogue ----
    float maskmul = g_sc[0], noisemul = g_sc[1];
    float wa = g_sc[4], wb = g_sc[5], wc = g_sc[6];
    uint2 kn = g_keys[1];
    const float* gmSb = stage;
    const float* gnSb = stage + 128 * STG;
    for (int i = tid; i < 8192; i += 256) {
        int r = i >> 6, c = i & 63;
        int b = m0 + r;
        int col = n0 + c;
        int f = c, l = l_idx;
        int wpb = g_wp[b], shb = g_sh[b];
        int idx;
        if (shb > 0)      idx = (l >= wpb) ? min(l + shb, LL - 1) : l;
        else if (shb < 0) idx = (l >= wpb + shb && l < LL + shb) ? (l - shb) : l;
        else              idx = l;
        uint32_t e = (uint32_t)b * LF + (uint32_t)col;
        float gm = gmSb[r * STG + c] + bmv[col];
        float mask = 1.0f - (1.0f - sigmf(gm)) * maskmul;
        float gn = gnSb[r * STG + c] + bnv[col];
        float nm = softplusf(gn);
        float nv = tf_normal(kn, e);
        float xv = x[(size_t)e];
        float wv = x[(size_t)b * LF + (size_t)idx * FF + f];
        float fv = g_freq[(size_t)e];
        float sc = g_scale[b * FF + f];
        out[(size_t)e] = (xv * mask * sc + nv * nm * noisemul) * wa + fv * wb + wv * wc;
    }
}

// ---------------- launch ------------------------------------------------------
extern "C" void kernel_launch(void* const* d_in, const int* in_sizes, int n_in,
                              void* d_out, int out_size) {
    const float* x   = (const float*)d_in[0];
    const float* w1  = (const float*)d_in[2];
    const float* b1  = (const float*)d_in[3];
    const float* w2  = (const float*)d_in[4];
    const float* b2  = (const float*)d_in[5];
    const float* w3  = (const float*)d_in[6];
    const float* b3  = (const float*)d_in[7];
    const float* wm  = (const float*)d_in[8];
    const float* bm  = (const float*)d_in[9];
    const float* wn  = (const float*)d_in[10];
    const float* bn  = (const float*)d_in[11];
    const float* ws  = (const float*)d_in[12];
    const float* bs  = (const float*)d_in[13];
    const float* pm  = (const float*)d_in[14];
    const float* pn  = (const float*)d_in[15];
    const float* psh = (const float*)d_in[16];
    const float* psc = (const float*)d_in[17];
    float* out = (float*)d_out;

    cudaFuncSetAttribute(final_mma, cudaFuncAttributeMaxDynamicSharedMemorySize, DYN_SMEM);

    setup_kernel<<<1, 256>>>(pm, pn, psh, psc);
    fft_mlp<<<2304, 256>>>(x, w1, b1, w2, b2, w3, b3, ws, bs);
    final_mma<<<dim3(512, 2), 256, DYN_SMEM>>>(x, wm, bm, wn, bn, out);
}

// round 11
// speedup vs baseline: 1.7243x; 1.0955x over previous
#include <cuda_runtime.h>
#include <cuda_bf16.h>
#include <mma.h>
#include <cstdint>

using namespace nvcuda;

#define BB   256
#define LL   512
#define FF   64
#define LF   32768
#define NTOT 8388608
#define HH   128
#define H2   256
#define ND   64

// ---------------- device globals ----------------
__device__ __align__(16) uint32_t g_h3b[BB * (H2 / 2)];   // h3 bf16: [256 rows][256]
__device__ float  g_scale[BB * FF];
__device__ float  g_freq[NTOT];

// ---------------- threefry2x32 (JAX) ----------------
__device__ __forceinline__ uint2 tf2x32(uint32_t k0, uint32_t k1, uint32_t x0, uint32_t x1) {
    uint32_t k2 = k0 ^ k1 ^ 0x1BD11BDAu;
    x0 += k0; x1 += k1;
#define TFR(r) { x0 += x1; x1 = (x1 << (r)) | (x1 >> (32 - (r))); x1 ^= x0; }
    TFR(13) TFR(15) TFR(26) TFR(6)
    x0 += k1; x1 += k2 + 1u;
    TFR(17) TFR(29) TFR(16) TFR(24)
    x0 += k2; x1 += k0 + 2u;
    TFR(13) TFR(15) TFR(26) TFR(6)
    x0 += k0; x1 += k1 + 3u;
    TFR(17) TFR(29) TFR(16) TFR(24)
    x0 += k1; x1 += k2 + 4u;
    TFR(13) TFR(15) TFR(26) TFR(6)
    x0 += k2; x1 += k0 + 5u;
#undef TFR
    return make_uint2(x0, x1);
}
__device__ __forceinline__ uint32_t tf_bits(uint2 key, uint32_t e) {
    uint2 r = tf2x32(key.x, key.y, 0u, e);
    return r.x ^ r.y;
}
__device__ __forceinline__ float u01_from_bits(uint32_t bits) {
    return __uint_as_float((bits >> 9) | 0x3f800000u) - 1.0f;
}
__device__ __forceinline__ float tf_normal(uint2 key, uint32_t e) {
    float u = u01_from_bits(tf_bits(key, e));
    const float lo = -0.99999994f;
    float v = u * 2.0f + lo;
    v = fmaxf(lo, v);
    return 1.4142135623730951f * erfinvf(v);
}
__device__ __forceinline__ float sigmf(float x)  { return 1.0f / (1.0f + expf(-x)); }
__device__ __forceinline__ float softplusf(float x) { return fmaxf(x, 0.0f) + log1pf(expf(-fabsf(x))); }

__device__ __forceinline__ float2 cadd(float2 a, float2 b) { return make_float2(a.x + b.x, a.y + b.y); }
__device__ __forceinline__ float2 csub(float2 a, float2 b) { return make_float2(a.x - b.x, a.y - b.y); }
__device__ __forceinline__ float2 cmul(float2 a, float2 w) { return make_float2(a.x * w.x - a.y * w.y, a.x * w.y + a.y * w.x); }
// conj(w) * b
__device__ __forceinline__ float2 cmulc(float2 w, float2 b) { return make_float2(w.x * b.x + w.y * b.y, w.x * b.y - w.y * b.x); }

// ---------------- kernel 1: FFT-aug (blocks 0..2047) + MLP (2048..2303) -----
__global__ __launch_bounds__(256) void fft_mlp(
    const float* __restrict__ x,
    const float* __restrict__ w1, const float* __restrict__ b1,
    const float* __restrict__ w2, const float* __restrict__ b2,
    const float* __restrict__ w3, const float* __restrict__ b3,
    const float* __restrict__ ws, const float* __restrict__ bs,
    const float* __restrict__ psh, const float* __restrict__ psc)
{
    __shared__ float2 s[512][9];
    __shared__ float2 tw[256];
    __shared__ float zb[ND], h1b[HH], h2b[H2], h3b[H2];
    int tid = threadIdx.x;

    if (blockIdx.x >= 2048) {
        // ------- MLP path -------
        int m = blockIdx.x - 2048, t = tid;
        uint2 kz = tf2x32(0u, 42u, 0u, 0u);
        if (t < ND) zb[t] = tf_normal(kz, (uint32_t)(m * ND + t));
        __syncthreads();
        if (t < HH) {
            float acc = b1[t];
#pragma unroll 8
            for (int k = 0; k < ND; k++) acc = fmaf(zb[k], w1[k * HH + t], acc);
            h1b[t] = acc > 0.0f ? acc : 0.2f * acc;
        }
        __syncthreads();
        {
            float acc = b2[t];
#pragma unroll 8
            for (int k = 0; k < HH; k++) acc = fmaf(h1b[k], w2[k * H2 + t], acc);
            h2b[t] = acc > 0.0f ? acc : 0.2f * acc;
        }
        __syncthreads();
        {
            float acc = b3[t];
#pragma unroll 8
            for (int k = 0; k < H2; k++) acc = fmaf(h2b[k], w3[k * H2 + t], acc);
            h3b[t] = acc > 0.0f ? acc : 0.2f * acc;
        }
        __syncthreads();
        if (t < H2 / 2) {
            __nv_bfloat162 p = __floats2bfloat162_rn(h3b[2 * t], h3b[2 * t + 1]);
            g_h3b[m * (H2 / 2) + t] = *reinterpret_cast<uint32_t*>(&p);
        }
        if (t < FF) {
            float s_scale = sigmf(*psc);
            float acc = bs[t];
#pragma unroll 8
            for (int k = 0; k < H2; k++) acc = fmaf(h3b[k], ws[k * FF + t], acc);
            g_scale[m * FF + t] = 1.0f + (softplusf(acc) - 0.5f) * 0.2f * s_scale;
        }
        return;
    }

    // ------- FFT path: 8 f-columns per block, DIF fwd -> mask -> DIT inv -------
    float ss_ = sigmf(*psh);
    float smix = 1.0f - ss_;
    float ratio = fminf(smix * 0.1f, 0.5f);
    uint2 kf = tf2x32(0u, 42u, 0u, 4u);

    int bidx = blockIdx.x;
    int b = bidx >> 3;
    int f0 = (bidx & 7) * 8;
    const float* xp = x + (size_t)b * LF + f0;
    {
        float sv, cv;
        sincosf(-6.283185307179586f * (float)tid / 512.0f, &sv, &cv);
        tw[tid] = make_float2(cv, sv);
    }
#pragma unroll
    for (int it = 0; it < 16; it++) {
        int u = it * 256 + tid;
        int ff = u & 7, l = u >> 3;
        s[l][ff] = make_float2(xp[(size_t)l * FF + ff], 0.0f);
    }
    __syncthreads();
    // forward DIF, stages fused in pairs (0,1),(2,3),(4,5),(6,7)
#pragma unroll
    for (int st = 0; st < 8; st += 2) {
        const int half  = 256 >> st;
        const int half2 = 128 >> st;
#pragma unroll
        for (int it = 0; it < 4; it++) {
            int u = it * 256 + tid;        // 1024 groups
            int ff = u & 7, gi = u >> 3;   // gi in [0,128)
            int k2 = gi & (half2 - 1);
            int g  = gi >> (7 - st);
            int p0 = (g << (9 - st)) + k2;
            float2 a0 = s[p0][ff], a1 = s[p0 + half2][ff];
            float2 a2 = s[p0 + half][ff], a3 = s[p0 + half + half2][ff];
            float2 w02 = tw[k2 << st];
            float2 w13 = tw[(k2 + half2) << st];
            float2 wnx = tw[k2 << (st + 1)];
            float2 A0 = cadd(a0, a2);
            float2 A2 = cmul(csub(a0, a2), w02);
            float2 A1 = cadd(a1, a3);
            float2 A3 = cmul(csub(a1, a3), w13);
            s[p0][ff]                 = cadd(A0, A1);
            s[p0 + half2][ff]         = cmul(csub(A0, A1), wnx);
            s[p0 + half][ff]          = cadd(A2, A3);
            s[p0 + half + half2][ff]  = cmul(csub(A2, A3), wnx);
        }
        __syncthreads();
    }
    // final radix-2 stage (st=8, half=1, w=1)
#pragma unroll
    for (int it = 0; it < 8; it++) {
        int u = it * 256 + tid;
        int ff = u & 7, bi = u >> 3;
        int p = bi << 1;
        float2 a = s[p][ff], bv = s[p + 1][ff];
        s[p][ff] = cadd(a, bv);
        s[p + 1][ff] = csub(a, bv);
    }
    __syncthreads();
    // keep mask at bit-reversed positions: freq j = brev9(p)
#pragma unroll
    for (int it = 0; it < 16; it++) {
        int u = it * 256 + tid;
        int ff = u & 7, p = u >> 3;
        int j = (int)(__brev((unsigned)p) >> 23);
        uint32_t e = (uint32_t)b * LF + (uint32_t)j * FF + (uint32_t)(f0 + ff);
        float uu = u01_from_bits(tf_bits(kf, e));
        if (!(uu > ratio)) s[p][ff] = make_float2(0.0f, 0.0f);
    }
    __syncthreads();
    // inverse DIT: single stage 0, then fused pairs (1,2),(3,4),(5,6),(7,8)
#pragma unroll
    for (int it = 0; it < 8; it++) {
        int u = it * 256 + tid;
        int ff = u & 7, bi = u >> 3;
        int p = bi << 1;
        float2 a = s[p][ff], bv = s[p + 1][ff];
        s[p][ff] = cadd(a, bv);
        s[p + 1][ff] = csub(a, bv);
    }
    __syncthreads();
#pragma unroll
    for (int st = 1; st < 9; st += 2) {
        const int half = 1 << st;
#pragma unroll
        for (int it = 0; it < 4; it++) {
            int u = it * 256 + tid;
            int ff = u & 7, gi = u >> 3;
            int k = gi & (half - 1);
            int g = gi >> st;
            int p0 = (g << (st + 2)) + k;
            float2 a0 = s[p0][ff], a1 = s[p0 + half][ff];
            float2 a2 = s[p0 + 2 * half][ff], a3 = s[p0 + 3 * half][ff];
            float2 wa_ = tw[k << (8 - st)];
            float2 wb_ = tw[k << (7 - st)];
            float2 wc_ = tw[(k + half) << (7 - st)];
            float2 t01 = cmulc(wa_, a1);
            float2 t23 = cmulc(wa_, a3);
            float2 A0 = cadd(a0, t01), A1 = csub(a0, t01);
            float2 A2 = cadd(a2, t23), A3 = csub(a2, t23);
            float2 tB = cmulc(wb_, A2), tC = cmulc(wc_, A3);
            s[p0][ff]             = cadd(A0, tB);
            s[p0 + 2 * half][ff]  = csub(A0, tB);
            s[p0 + half][ff]      = cadd(A1, tC);
            s[p0 + 3 * half][ff]  = csub(A1, tC);
        }
        __syncthreads();
    }
#pragma unroll
    for (int it = 0; it < 16; it++) {
        int u = it * 256 + tid;
        int ff = u & 7, l = u >> 3;
        float val = s[l][ff].x * (1.0f / 512.0f);
        if (smix < 0.01f) val = xp[(size_t)l * FF + ff];
        g_freq[(size_t)b * LF + (size_t)l * FF + f0 + ff] = val;
    }
}

// ---------------- kernel 2: wmma bf16 dual GEMM (M=256) + fused epilogue ----
// grid 512 CTAs, 512 threads (16 warps). Per CTA: M=256, N=64, K=256.
#define BPLD 72
#define STG  68
#define SM_PAN_N 36864
#define SM_ST    73728
#define DYN_SMEM (73728 + 2 * 256 * STG * 4)   // 212992 B

__global__ __launch_bounds__(512) void final_mma(
    const float* __restrict__ x,
    const float* __restrict__ wm, const float* __restrict__ bmv,
    const float* __restrict__ wn, const float* __restrict__ bnv,
    float* __restrict__ out,
    const float* __restrict__ pm, const float* __restrict__ pn,
    const float* __restrict__ psh)
{
    extern __shared__ char smem[];
    __nv_bfloat16* Bm = reinterpret_cast<__nv_bfloat16*>(smem);
    __nv_bfloat16* Bn = reinterpret_cast<__nv_bfloat16*>(smem + SM_PAN_N);
    float* stage = reinterpret_cast<float*>(smem + SM_ST);
    __shared__ int swp[256], ssh[256];
    int tid = threadIdx.x;
    int wid = tid >> 5;
    int n0 = blockIdx.x * 64;
    int l_idx = blockIdx.x;
    const __nv_bfloat16* Ag = reinterpret_cast<const __nv_bfloat16*>(g_h3b);

    // ---- per-CTA wp/sh randint (same arithmetic as verified setup) ----
    if (tid < 256) {
        float ss_ = sigmf(*psh);
        int ws_ = (int)(51.2f * ss_);
        uint2 kwp = tf2x32(0u, 42u, 0u, 2u);
        uint2 ksh = tf2x32(0u, 42u, 0u, 3u);
        uint2 skwp1 = tf2x32(kwp.x, kwp.y, 0u, 0u);
        uint2 skwp2 = tf2x32(kwp.x, kwp.y, 0u, 1u);
        uint2 sksh1 = tf2x32(ksh.x, ksh.y, 0u, 0u);
        uint2 sksh2 = tf2x32(ksh.x, ksh.y, 0u, 1u);
        {
            uint32_t span = (uint32_t)max(1, (512 - ws_) - ws_);
            uint32_t mult = 65536u % span; mult = (mult * mult) % span;
            uint32_t hi = tf_bits(skwp1, (uint32_t)tid);
            uint32_t lo = tf_bits(skwp2, (uint32_t)tid);
            uint32_t off = ((hi % span) * mult + (lo % span)) % span;
            swp[tid] = ws_ + (int)off;
        }
        {
            uint32_t span = (uint32_t)(2 * ws_ + 1); if (span == 0u) span = 1u;
            uint32_t mult = 65536u % span; mult = (mult * mult) % span;
            uint32_t hi = tf_bits(sksh1, (uint32_t)tid);
            uint32_t lo = tf_bits(sksh2, (uint32_t)tid);
            uint32_t off = ((hi % span) * mult + (lo % span)) % span;
            ssh[tid] = -ws_ + (int)off;
        }
    }

    // ---- preload BOTH panels: K=256 x N=64 fp32 -> bf16 smem, loaded once ----
#pragma unroll
    for (int i = 0; i < 4; i++) {
        int u = i * 512 + tid;               // 2048 chunks of 8 floats
        int r = u >> 3, c = (u & 7) * 8;
        {
            const float4* src = reinterpret_cast<const float4*>(wm + (size_t)r * LF + n0 + c);
            float4 v0 = src[0], v1 = src[1];
            __nv_bfloat162 p0 = __floats2bfloat162_rn(v0.x, v0.y);
            __nv_bfloat162 p1 = __floats2bfloat162_rn(v0.z, v0.w);
            __nv_bfloat162 p2 = __floats2bfloat162_rn(v1.x, v1.y);
            __nv_bfloat162 p3 = __floats2bfloat162_rn(v1.z, v1.w);
            uint4 pk = make_uint4(*reinterpret_cast<uint32_t*>(&p0), *reinterpret_cast<uint32_t*>(&p1),
                                  *reinterpret_cast<uint32_t*>(&p2), *reinterpret_cast<uint32_t*>(&p3));
            *reinterpret_cast<uint4*>(Bm + r * BPLD + c) = pk;
        }
        {
            const float4* src = reinterpret_cast<const float4*>(wn + (size_t)r * LF + n0 + c);
            float4 v0 = src[0], v1 = src[1];
            __nv_bfloat162 p0 = __floats2bfloat162_rn(v0.x, v0.y);
            __nv_bfloat162 p1 = __floats2bfloat162_rn(v0.z, v0.w);
            __nv_bfloat162 p2 = __floats2bfloat162_rn(v1.x, v1.y);
            __nv_bfloat162 p3 = __floats2bfloat162_rn(v1.z, v1.w);
            uint4 pk = make_uint4(*reinterpret_cast<uint32_t*>(&p0), *reinterpret_cast<uint32_t*>(&p1),
                                  *reinterpret_cast<uint32_t*>(&p2), *reinterpret_cast<uint32_t*>(&p3));
            *reinterpret_cast<uint4*>(Bn + r * BPLD + c) = pk;
        }
    }
    __syncthreads();

    // ---- GEMMs: 16 warps, each owns 16 rows of M=256 ----
#pragma unroll
    for (int gsel = 0; gsel < 2; gsel++) {
        const __nv_bfloat16* Bt = gsel ? Bn : Bm;
        wmma::fragment<wmma::accumulator, 16, 16, 16, float> acc[4];
#pragma unroll
        for (int ni = 0; ni < 4; ni++) wmma::fill_fragment(acc[ni], 0.0f);
#pragma unroll
        for (int kt = 0; kt < 16; kt++) {
            wmma::fragment<wmma::matrix_a, 16, 16, 16, __nv_bfloat16, wmma::row_major> af;
            wmma::load_matrix_sync(af, Ag + (size_t)(wid * 16) * H2 + kt * 16, H2);
#pragma unroll
            for (int ni = 0; ni < 4; ni++) {
                wmma::fragment<wmma::matrix_b, 16, 16, 16, __nv_bfloat16, wmma::row_major> bf;
                wmma::load_matrix_sync(bf, Bt + (size_t)kt * 16 * BPLD + ni * 16, BPLD);
                wmma::mma_sync(acc[ni], af, bf, acc[ni]);
            }
        }
        float* stg = stage + gsel * 256 * STG;
#pragma unroll
        for (int ni = 0; ni < 4; ni++)
            wmma::store_matrix_sync(stg + (size_t)(wid * 16) * STG + ni * 16, acc[ni], STG, wmma::mem_row_major);
    }
    __syncthreads();

    // ---- fused epilogue ----
    float maskmul = sigmf(*pm) * 0.3f;
    float noisemul = sigmf(*pn) * 0.05f;
    float ss_ = sigmf(*psh);
    float smix = 1.0f - ss_;
    float wa = fminf(fmaxf(1.0f - smix - ss_, 0.1f), 0.8f);
    float wb = smix * 0.5f, wc = ss_ * 0.5f;
    float tot = wa + wb + wc;
    wa /= tot; wb /= tot; wc /= tot;
    uint2 kn = tf2x32(0u, 42u, 0u, 1u);
    const float* gmSb = stage;
    const float* gnSb = stage + 256 * STG;
    for (int i = tid; i < 16384; i += 512) {
        int r = i >> 6, c = i & 63;
        int b = r;
        int col = n0 + c;
        int f = c, l = l_idx;
        int wpb = swp[b], shb = ssh[b];
        int idx;
        if (shb > 0)      idx = (l >= wpb) ? min(l + shb, LL - 1) : l;
        else if (shb < 0) idx = (l >= wpb + shb && l < LL + shb) ? (l - shb) : l;
        else              idx = l;
        uint32_t e = (uint32_t)b * LF + (uint32_t)col;
        float gm = gmSb[r * STG + c] + bmv[col];
        float mask = 1.0f - (1.0f - sigmf(gm)) * maskmul;
        float gn = gnSb[r * STG + c] + bnv[col];
        float nm = softplusf(gn);
        float nv = tf_normal(kn, e);
        float xv = x[(size_t)e];
        float wv = x[(size_t)b * LF + (size_t)idx * FF + f];
        float fv = g_freq[(size_t)e];
        float sc = g_scale[b * FF + f];
        out[(size_t)e] = (xv * mask * sc + nv * nm * noisemul) * wa + fv * wb + wv * wc;
    }
}

// ---------------- launch ------------------------------------------------------
extern "C" void kernel_launch(void* const* d_in, const int* in_sizes, int n_in,
                              void* d_out, int out_size) {
    const float* x   = (const float*)d_in[0];
    const float* w1  = (const float*)d_in[2];
    const float* b1  = (const float*)d_in[3];
    const float* w2  = (const float*)d_in[4];
    const float* b2  = (const float*)d_in[5];
    const float* w3  = (const float*)d_in[6];
    const float* b3  = (const float*)d_in[7];
    const float* wm  = (const float*)d_in[8];
    const float* bm  = (const float*)d_in[9];
    const float* wn  = (const float*)d_in[10];
    const float* bn  = (const float*)d_in[11];
    const float* ws  = (const float*)d_in[12];
    const float* bs  = (const float*)d_in[13];
    const float* pm  = (const float*)d_in[14];
    const float* pn  = (const float*)d_in[15];
    const float* psh = (const float*)d_in[16];
    const float* psc = (const float*)d_in[17];
    float* out = (float*)d_out;

    cudaFuncSetAttribute(final_mma, cudaFuncAttributeMaxDynamicSharedMemorySize, DYN_SMEM);

    fft_mlp<<<2304, 256>>>(x, w1, b1, w2, b2, w3, b3, ws, bs, psh, psc);
    final_mma<<<512, 512, DYN_SMEM>>>(x, wm, bm, wn, bn, out, pm, pn, psh);
}